// round 13
// baseline (speedup 1.0000x reference)
#include <cuda_runtime.h>
#include <cuda_bf16.h>
#include <stdint.h>

// ---------------------------------------------------------------------------
// SSD head via mma.sync m16n8k8 TF32, round 13:
// smem re-laid out in LDSM-native order [k8-pair][k-half][row][16B]:
//  - no XOR swizzle anywhere in the hot loop (addresses linear in k8 ->
//    folded into LDSM immediates; in-loop address ALU ~= 0)
//  - cp.async B writes linear (always conflict-free), A STS consecutive 16B
//  - LDSM reads 8 consecutive 16B rows -> conflict-free
// 512 thr / 16 warps, warp = 2 m-tiles x 5 n-tiles. Double-buffered
// (cp.async B + pipelined A gather). Epilogue: bias+decode+softmax fused.
// ---------------------------------------------------------------------------

#define NUM_PRIORS 11640
#define NTH 512
#define NB 160                          // padded output channels (20 n-tiles)
// A tile: 8 pairs x 2 halves x 128 rows x 16B
#define A_PAIR 4096                     // 2*128*16
#define A_HALF 2048                     // 128*16
#define ATILE (8 * A_PAIR)              // 32768
// B tile: 8 pairs x 2 halves x 160 rows x 16B
#define B_PAIR 5120                     // 2*160*16
#define B_HALF 2560                     // 160*16
#define BTILE (8 * B_PAIR)              // 40960
#define TOTAL_WCHUNKS 396
#define TOTAL_BLOCKS 488
#define A_OFF 0
#define B_OFF ATILE
#define BUFSZ (ATILE + BTILE)           // 73728
#define SMEM_BYTES (2 * BUFSZ)          // 147456
#define DSTRIDE 161

__device__ __constant__ int d_C[6]    = {512,1024,512,256,256,256};
__device__ __constant__ int d_logC[6] = {9,10,9,8,8,8};
__device__ __constant__ int d_F[6]    = {38,19,10,5,3,1};
__device__ __constant__ int d_FF[6]   = {1444,361,100,25,9,1};
__device__ __constant__ int d_N[6]    = {46208,11552,3200,800,288,32};
__device__ __constant__ int d_nch[6]  = {72,144,72,36,36,36};
__device__ __constant__ int d_wch0[6] = {0,72,216,288,324,360};
__device__ __constant__ int d_poff[6] = {0,8664,10830,11430,11580,11634};
__device__ __constant__ int d_bstart[7] = {0,91,452,477,484,487,488};
__device__ __constant__ int d_border[6] = {1,0,2,3,4,5};

__device__ unsigned char g_wbf[(size_t)TOTAL_WCHUNKS * BTILE];

struct WParams { const float* lw[6]; const float* cw[6]; };
struct CParams { const float* feat[6]; const float* lb[6]; const float* cb[6]; };

// ---- PTX helpers ------------------------------------------------------------
__device__ __forceinline__ uint32_t smaddr(const void* p) {
    return (uint32_t)__cvta_generic_to_shared(p);
}
__device__ __forceinline__ uint32_t to_tf32(float x) {
    uint32_t u;
    asm("cvt.rna.tf32.f32 %0, %1;" : "=r"(u) : "f"(x));
    return u;
}
__device__ __forceinline__ void ldsm4(uint32_t* r, uint32_t a) {
    asm volatile("ldmatrix.sync.aligned.m8n8.x4.shared.b16 {%0,%1,%2,%3}, [%4];"
                 : "=r"(r[0]), "=r"(r[1]), "=r"(r[2]), "=r"(r[3]) : "r"(a));
}
__device__ __forceinline__ void ldsm2(uint32_t* r, uint32_t a) {
    asm volatile("ldmatrix.sync.aligned.m8n8.x2.shared.b16 {%0,%1}, [%2];"
                 : "=r"(r[0]), "=r"(r[1]) : "r"(a));
}
__device__ __forceinline__ void mma_tf32(float* d, const uint32_t* a, const uint32_t* b) {
    asm volatile("mma.sync.aligned.m16n8k8.row.col.f32.tf32.tf32.f32 "
                 "{%0,%1,%2,%3},{%4,%5,%6,%7},{%8,%9},{%0,%1,%2,%3};"
                 : "+f"(d[0]), "+f"(d[1]), "+f"(d[2]), "+f"(d[3])
                 : "r"(a[0]), "r"(a[1]), "r"(a[2]), "r"(a[3]),
                   "r"(b[0]), "r"(b[1]));
}
__device__ __forceinline__ void cpasync16(uint32_t dst, const void* src) {
    asm volatile("cp.async.cg.shared.global [%0], [%1], 16;"
                 :: "r"(dst), "l"(src) : "memory");
}
__device__ __forceinline__ void cpcommit() {
    asm volatile("cp.async.commit_group;" ::: "memory");
}
__device__ __forceinline__ void cpwait0() {
    asm volatile("cp.async.wait_group 0;" ::: "memory");
}

// ---- weight preprocessing: RNA tf32 in LDSM-native layout -------------------
__global__ __launch_bounds__(256) void prep_weights(WParams P)
{
    int ch = blockIdx.x;
    int s = 0;
    #pragma unroll
    for (int i = 1; i < 6; i++) if (ch >= d_wch0[i]) s = i;
    int cis = ch - d_wch0[s];
    int C = d_C[s];
    int K = C * 9;
    int k0 = cis * 64;
    int kk = k0 >> d_logC[s];
    int c0 = k0 & (C - 1);
    size_t base = (size_t)ch * BTILE;

    for (int e = threadIdx.x; e < NB * 64; e += blockDim.x) {
        int row = e >> 6;
        int col = e & 63;                 // k within chunk
        float v = 0.f;
        if (row < 150) {
            int widx = (c0 + col) * 9 + kk;
            v = (row < 24) ? P.lw[s][(size_t)row * K + widx]
                           : P.cw[s][(size_t)(row - 24) * K + widx];
        }
        int gg = col >> 2;                // granule 0..15
        uint32_t off = (uint32_t)(gg >> 1) * B_PAIR + (uint32_t)(gg & 1) * B_HALF
                     + (uint32_t)row * 16 + (uint32_t)(col & 3) * 4;
        *(uint32_t*)(g_wbf + base + off) = to_tf32(v);
    }
}

// ---- main fused kernel --------------------------------------------------------
__global__ __launch_bounds__(NTH, 1) void ssd_tf32_kernel(
    CParams P, const float* __restrict__ priors, float* __restrict__ out)
{
    extern __shared__ __align__(16) unsigned char sm[];
    float* Dsm = (float*)sm;
    const uint32_t smb = smaddr(sm);

    const int tid = threadIdx.x;
    const int wid = tid >> 5;
    const int lane = tid & 31;
    const int mg = wid & 3;               // m-group: 32 pixels (2 m-tiles)
    const int ng = wid >> 2;              // n-group: 5 tiles
    const int gbase = ng * 5;

    // ---- block -> (stage, pixel tile) ----
    int bid = blockIdx.x;
    int oi = 0;
    #pragma unroll
    for (int i = 1; i < 6; i++) if (bid >= d_bstart[i]) oi = i;
    const int s = d_border[oi];
    const int pix0 = (bid - d_bstart[oi]) * 128;

    const int C = d_C[s], logC = d_logC[s], F = d_F[s], FF = d_FF[s], N = d_N[s];
    const int nch = d_nch[s], wch0 = d_wch0[s];
    const float* __restrict__ feat = P.feat[s];

    // ---- A gather: 4 threads per pixel, 16 k-values each (coalesced) ----
    const int arow = tid & 127;             // pixel row in tile
    const int kq   = tid >> 7;              // 0..3: k offset 0/16/32/48
    const int apix = pix0 + arow;
    const bool aok = (apix < N);
    int ab = 0, ay = 0, ax = 0;
    if (aok) {
        ab = apix / FF;
        int r = apix - ab * FF;
        ay = r / F;
        ax = r - ay * F;
    }
    const float* fb0 = feat + (size_t)ab * C * FF;

    // ---- ldmatrix lane components ----
    const int a_mloc = (lane & 7) + ((lane >> 3) & 1) * 8;   // row within m-tile
    const int a_kg   = lane >> 4;                             // k half
    const int b_r    = lane & 7;
    const int b_half = (lane >> 3) & 1;
    const int b_tl   = (lane >> 4) & 1;

    float acc[2][5][4];
    #pragma unroll
    for (int mt = 0; mt < 2; mt++)
        #pragma unroll
        for (int nt = 0; nt < 5; nt++)
            #pragma unroll
            for (int q = 0; q < 4; q++) acc[mt][nt][q] = 0.f;

    // ---------------- helpers ----------------
    auto copyB = [&](int ch, int buf) {
        const uint4* src = (const uint4*)(g_wbf + (size_t)(wch0 + ch) * BTILE);
        uint32_t dst = smb + buf * BUFSZ + B_OFF;
        #pragma unroll
        for (int i = tid; i < BTILE / 16; i += NTH)
            cpasync16(dst + i * 16, src + i);
    };
    float xg[16];
    auto gatherA = [&](int ch) {
        int k0 = ch * 64;
        int kk = k0 >> logC;
        int c0 = k0 & (C - 1);
        int ky = kk / 3, kx = kk - ky * 3;
        int iy = ay + ky - 1, ix = ax + kx - 1;
        bool v = aok && ((unsigned)iy < (unsigned)F) && ((unsigned)ix < (unsigned)F);
        const float* bp = fb0 + (size_t)(c0 + kq * 16) * FF + iy * F + ix;
        #pragma unroll
        for (int j = 0; j < 16; j++)
            xg[j] = v ? __ldg(bp + (size_t)j * FF) : 0.f;
    };
    auto storeA = [&](int buf) {
        uint32_t base = smb + buf * BUFSZ + A_OFF + (uint32_t)arow * 16;
        #pragma unroll
        for (int g = 0; g < 4; g++) {                 // granule gg = kq*4+g
            uint32_t t0 = to_tf32(xg[g * 4 + 0]);
            uint32_t t1 = to_tf32(xg[g * 4 + 1]);
            uint32_t t2 = to_tf32(xg[g * 4 + 2]);
            uint32_t t3 = to_tf32(xg[g * 4 + 3]);
            int gg = kq * 4 + g;
            uint32_t off = (uint32_t)(gg >> 1) * A_PAIR + (uint32_t)(gg & 1) * A_HALF;
            asm volatile("st.shared.v4.b32 [%0], {%1,%2,%3,%4};"
                         :: "r"(base + off), "r"(t0), "r"(t1), "r"(t2), "r"(t3)
                         : "memory");
        }
    };
    auto compute = [&](int buf) {
        // hoisted base addresses; k8 advance is a compile-time immediate
        uint32_t aAd0 = smb + buf * BUFSZ + A_OFF
                      + (uint32_t)a_kg * A_HALF
                      + (uint32_t)(mg * 32 + a_mloc) * 16;
        uint32_t aAd1 = aAd0 + 16 * 16;
        const uint32_t bB = smb + buf * BUFSZ + B_OFF + (uint32_t)b_half * B_HALF;
        uint32_t bAd0 = bB + (uint32_t)((gbase + 0 + b_tl) * 8 + b_r) * 16;
        uint32_t bAd1 = bB + (uint32_t)((gbase + 2 + b_tl) * 8 + b_r) * 16;
        uint32_t bAd2 = bB + (uint32_t)((gbase + 4) * 8 + b_r) * 16;
        #pragma unroll
        for (int k8 = 0; k8 < 8; k8++) {
            uint32_t a0[4], a1[4];
            ldsm4(a0, aAd0 + k8 * A_PAIR);
            ldsm4(a1, aAd1 + k8 * A_PAIR);
            uint32_t b0[4], b1[4], b2[2];
            ldsm4(b0, bAd0 + k8 * B_PAIR);
            ldsm4(b1, bAd1 + k8 * B_PAIR);
            ldsm2(b2, bAd2 + k8 * B_PAIR);
            mma_tf32(acc[0][0], a0, b0);
            mma_tf32(acc[1][0], a1, b0);
            mma_tf32(acc[0][1], a0, b0 + 2);
            mma_tf32(acc[1][1], a1, b0 + 2);
            mma_tf32(acc[0][2], a0, b1);
            mma_tf32(acc[1][2], a1, b1);
            mma_tf32(acc[0][3], a0, b1 + 2);
            mma_tf32(acc[1][3], a1, b1 + 2);
            mma_tf32(acc[0][4], a0, b2);
            mma_tf32(acc[1][4], a1, b2);
        }
    };

    // ---------------- pipeline ----------------
    copyB(0, 0);
    cpcommit();
    gatherA(0);
    storeA(0);
    cpwait0();
    __syncthreads();

    for (int ch = 0; ch < nch; ch++) {
        int cur = ch & 1;
        bool pf = (ch + 1 < nch);
        if (pf) {
            copyB(ch + 1, cur ^ 1);
            cpcommit();
            gatherA(ch + 1);        // LDGs in flight during MMAs
        }
        compute(cur);
        if (pf) storeA(cur ^ 1);    // round + STS after MMAs
        cpwait0();
        __syncthreads();
    }

    // ---- write accumulators to smem D[128][DSTRIDE] ----
    #pragma unroll
    for (int mt = 0; mt < 2; mt++)
        #pragma unroll
        for (int nt = 0; nt < 5; nt++) {
            int r = mg * 32 + mt * 16 + (lane >> 2);
            int c = (gbase + nt) * 8 + (lane & 3) * 2;
            Dsm[r * DSTRIDE + c]           = acc[mt][nt][0];
            Dsm[r * DSTRIDE + c + 1]       = acc[mt][nt][1];
            Dsm[(r + 8) * DSTRIDE + c]     = acc[mt][nt][2];
            Dsm[(r + 8) * DSTRIDE + c + 1] = acc[mt][nt][3];
        }
    __syncthreads();

    // ---- per-pixel bias + decode + softmax ----
    if (tid < 128) {
        int n = pix0 + tid;
        if (n < N) {
            const float* drow = Dsm + tid * DSTRIDE;
            int b = n / FF;
            int r = n - b * FF;
            int pbase = d_poff[s] + r * 6;
            float* ob = out + ((size_t)b * NUM_PRIORS + pbase) * 25;
            const float* lb = P.lb[s];
            const float* cb = P.cb[s];
            #pragma unroll
            for (int pic = 0; pic < 6; pic++) {
                const float* pr = priors + (size_t)(pbase + pic) * 4;
                float prx = __ldg(pr + 0), pry = __ldg(pr + 1);
                float prz = __ldg(pr + 2), prw = __ldg(pr + 3);
                float lx = drow[pic * 4 + 0] + __ldg(lb + pic * 4 + 0);
                float ly = drow[pic * 4 + 1] + __ldg(lb + pic * 4 + 1);
                float lw_ = drow[pic * 4 + 2] + __ldg(lb + pic * 4 + 2);
                float lh_ = drow[pic * 4 + 3] + __ldg(lb + pic * 4 + 3);
                float cx = prx + lx * 0.1f * prz;
                float cy = pry + ly * 0.1f * prw;
                float w = prz * expf(lw_ * 0.2f);
                float h = prw * expf(lh_ * 0.2f);
                float mnx = cx - 0.5f * w;
                float mny = cy - 0.5f * h;
                float* o = ob + pic * 25;
                o[0] = mnx; o[1] = mny; o[2] = mnx + w; o[3] = mny + h;

                float vv[21];
                float mx = -1e30f;
                #pragma unroll
                for (int c2 = 0; c2 < 21; c2++) {
                    vv[c2] = drow[24 + pic * 21 + c2] + __ldg(cb + pic * 21 + c2);
                    mx = fmaxf(mx, vv[c2]);
                }
                float ssum = 0.f;
                #pragma unroll
                for (int c2 = 0; c2 < 21; c2++) { vv[c2] = expf(vv[c2] - mx); ssum += vv[c2]; }
                float inv = 1.f / ssum;
                #pragma unroll
                for (int c2 = 0; c2 < 21; c2++) o[4 + c2] = vv[c2] * inv;
            }
        }
    }
}

// ---------------------------------------------------------------------------
extern "C" void kernel_launch(void* const* d_in, const int* in_sizes, int n_in,
                              void* d_out, int out_size)
{
    CParams cp;
    WParams wp;
    const float* priors;

    bool interleaved = (n_in == 31) && (in_sizes[2] == 24);
    if (interleaved) {
        for (int s = 0; s < 6; s++) {
            cp.feat[s] = (const float*)d_in[s * 5 + 0];
            wp.lw[s]   = (const float*)d_in[s * 5 + 1];
            cp.lb[s]   = (const float*)d_in[s * 5 + 2];
            wp.cw[s]   = (const float*)d_in[s * 5 + 3];
            cp.cb[s]   = (const float*)d_in[s * 5 + 4];
        }
        priors = (const float*)d_in[30];
    } else {
        for (int s = 0; s < 6; s++) {
            cp.feat[s] = (const float*)d_in[s];
            wp.lw[s]   = (const float*)d_in[6 + s];
            cp.lb[s]   = (const float*)d_in[12 + s];
            wp.cw[s]   = (const float*)d_in[18 + s];
            cp.cb[s]   = (const float*)d_in[24 + s];
        }
        priors = (const float*)d_in[30];
    }

    cudaFuncSetAttribute(ssd_tf32_kernel,
                         cudaFuncAttributeMaxDynamicSharedMemorySize, SMEM_BYTES);

    prep_weights<<<TOTAL_WCHUNKS, 256>>>(wp);
    ssd_tf32_kernel<<<TOTAL_BLOCKS, NTH, SMEM_BYTES>>>(cp, priors, (float*)d_out);
}

// round 14
// speedup vs baseline: 1.4738x; 1.4738x over previous
#include <cuda_runtime.h>
#include <cuda_fp16.h>
#include <stdint.h>

// ---------------------------------------------------------------------------
// SSD head via mma.sync m16n8k16 FP16 (single pass), round 14.
// fp16 mantissa == tf32 mantissa (10 bits) but K=16 per MMA instruction:
// halves the MMA count (25.1M) AND all smem traffic vs round 12's tf32.
// Structure = round 12 (best): XOR-granule swizzle, coalesced A gather,
// 512 thr / 16 warps, warp = 2 m-tiles x 5 n-tiles, double-buffered
// (cp.async B + pipelined A gather). Epilogue: bias+decode+softmax fused.
// ---------------------------------------------------------------------------

#define NUM_PRIORS 11640
#define NTH 512
#define RS 128                          // smem row stride bytes (64 fp16, 8 granules)
#define NB 160                          // padded output channels (20 n-tiles)
#define ATILE (128 * RS)                // 16384
#define BTILE (NB * RS)                 // 20480
#define TOTAL_WCHUNKS 396
#define TOTAL_BLOCKS 488
#define A_OFF 0
#define B_OFF ATILE
#define BUFSZ (ATILE + BTILE)           // 36864
#define SMEM_BYTES 82944                // max(2*BUFSZ=73728, Dsm=128*161*4=82432)
#define DSTRIDE 161

__device__ __constant__ int d_C[6]    = {512,1024,512,256,256,256};
__device__ __constant__ int d_logC[6] = {9,10,9,8,8,8};
__device__ __constant__ int d_F[6]    = {38,19,10,5,3,1};
__device__ __constant__ int d_FF[6]   = {1444,361,100,25,9,1};
__device__ __constant__ int d_N[6]    = {46208,11552,3200,800,288,32};
__device__ __constant__ int d_nch[6]  = {72,144,72,36,36,36};
__device__ __constant__ int d_wch0[6] = {0,72,216,288,324,360};
__device__ __constant__ int d_poff[6] = {0,8664,10830,11430,11580,11634};
__device__ __constant__ int d_bstart[7] = {0,91,452,477,484,487,488};
__device__ __constant__ int d_border[6] = {1,0,2,3,4,5};

__device__ unsigned char g_wbf[(size_t)TOTAL_WCHUNKS * BTILE];

struct WParams { const float* lw[6]; const float* cw[6]; };
struct CParams { const float* feat[6]; const float* lb[6]; const float* cb[6]; };

// ---- PTX helpers ------------------------------------------------------------
__device__ __forceinline__ uint32_t smaddr(const void* p) {
    return (uint32_t)__cvta_generic_to_shared(p);
}
__device__ __forceinline__ uint32_t pack_h2(float x, float y) {
    __half2 h = __floats2half2_rn(x, y);
    return *reinterpret_cast<uint32_t*>(&h);
}
__device__ __forceinline__ void ldsm4(uint32_t* r, uint32_t a) {
    asm volatile("ldmatrix.sync.aligned.m8n8.x4.shared.b16 {%0,%1,%2,%3}, [%4];"
                 : "=r"(r[0]), "=r"(r[1]), "=r"(r[2]), "=r"(r[3]) : "r"(a));
}
__device__ __forceinline__ void ldsm2(uint32_t* r, uint32_t a) {
    asm volatile("ldmatrix.sync.aligned.m8n8.x2.shared.b16 {%0,%1}, [%2];"
                 : "=r"(r[0]), "=r"(r[1]) : "r"(a));
}
__device__ __forceinline__ void mma_f16(float* d, const uint32_t* a, const uint32_t* b) {
    asm volatile("mma.sync.aligned.m16n8k16.row.col.f32.f16.f16.f32 "
                 "{%0,%1,%2,%3},{%4,%5,%6,%7},{%8,%9},{%0,%1,%2,%3};"
                 : "+f"(d[0]), "+f"(d[1]), "+f"(d[2]), "+f"(d[3])
                 : "r"(a[0]), "r"(a[1]), "r"(a[2]), "r"(a[3]),
                   "r"(b[0]), "r"(b[1]));
}
__device__ __forceinline__ void cpasync16(uint32_t dst, const void* src) {
    asm volatile("cp.async.cg.shared.global [%0], [%1], 16;"
                 :: "r"(dst), "l"(src) : "memory");
}
__device__ __forceinline__ void cpcommit() {
    asm volatile("cp.async.commit_group;" ::: "memory");
}
__device__ __forceinline__ void cpwait0() {
    asm volatile("cp.async.wait_group 0;" ::: "memory");
}

// swizzled byte offset of (row, 16B-granule g in 0..7) within a tile
__device__ __forceinline__ uint32_t swz(uint32_t row, uint32_t g) {
    return row * RS + ((g ^ (row & 7u)) << 4);
}

// ---- weight preprocessing: fp16, kk-major, swizzled rows --------------------
__global__ __launch_bounds__(256) void prep_weights(WParams P)
{
    int ch = blockIdx.x;
    int s = 0;
    #pragma unroll
    for (int i = 1; i < 6; i++) if (ch >= d_wch0[i]) s = i;
    int cis = ch - d_wch0[s];
    int C = d_C[s];
    int K = C * 9;
    int k0 = cis * 64;
    int kk = k0 >> d_logC[s];
    int c0 = k0 & (C - 1);
    size_t base = (size_t)ch * BTILE;

    for (int e = threadIdx.x; e < NB * 64; e += blockDim.x) {
        int row = e >> 6;
        int col = e & 63;                 // k within chunk (fp16 element)
        float v = 0.f;
        if (row < 150) {
            int widx = (c0 + col) * 9 + kk;
            v = (row < 24) ? P.lw[s][(size_t)row * K + widx]
                           : P.cw[s][(size_t)(row - 24) * K + widx];
        }
        uint32_t off = swz(row, col >> 3) + (col & 7) * 2;
        *(__half*)(g_wbf + base + off) = __float2half_rn(v);
    }
}

// ---- main fused kernel --------------------------------------------------------
__global__ __launch_bounds__(NTH, 1) void ssd_f16_kernel(
    CParams P, const float* __restrict__ priors, float* __restrict__ out)
{
    extern __shared__ __align__(16) unsigned char sm[];
    float* Dsm = (float*)sm;
    const uint32_t smb = smaddr(sm);

    const int tid = threadIdx.x;
    const int wid = tid >> 5;
    const int lane = tid & 31;
    const int mg = wid & 3;               // m-group: 32 pixels (2 m-tiles)
    const int ng = wid >> 2;              // n-group: 5 tiles
    const int gbase = ng * 5;

    // ---- block -> (stage, pixel tile) ----
    int bid = blockIdx.x;
    int oi = 0;
    #pragma unroll
    for (int i = 1; i < 6; i++) if (bid >= d_bstart[i]) oi = i;
    const int s = d_border[oi];
    const int pix0 = (bid - d_bstart[oi]) * 128;

    const int C = d_C[s], logC = d_logC[s], F = d_F[s], FF = d_FF[s], N = d_N[s];
    const int nch = d_nch[s], wch0 = d_wch0[s];
    const float* __restrict__ feat = P.feat[s];

    // ---- A gather: 4 threads per pixel, 16 k-values each (coalesced) ----
    const int arow = tid & 127;             // pixel row in tile
    const int kq   = tid >> 7;              // 0..3: k offset 0/16/32/48
    const int apix = pix0 + arow;
    const bool aok = (apix < N);
    int ab = 0, ay = 0, ax = 0;
    if (aok) {
        ab = apix / FF;
        int r = apix - ab * FF;
        ay = r / F;
        ax = r - ay * F;
    }
    const float* fb0 = feat + (size_t)ab * C * FF;

    // ---- ldmatrix lane components (validated bf16-k16 scheme) ----
    const int a_mloc = (lane & 7) + ((lane >> 3) & 1) * 8;   // row within m-tile
    const int a_kg   = lane >> 4;                             // k granule half
    const int b_nloc = (lane & 7) + ((lane >> 4) & 1) * 8;    // covers 2 n-tiles
    const int b_kg   = (lane >> 3) & 1;

    float acc[2][5][4];
    #pragma unroll
    for (int mt = 0; mt < 2; mt++)
        #pragma unroll
        for (int nt = 0; nt < 5; nt++)
            #pragma unroll
            for (int q = 0; q < 4; q++) acc[mt][nt][q] = 0.f;

    // ---------------- helpers ----------------
    auto copyB = [&](int ch, int buf) {
        const uint4* src = (const uint4*)(g_wbf + (size_t)(wch0 + ch) * BTILE);
        uint32_t dst = smb + buf * BUFSZ + B_OFF;
        #pragma unroll
        for (int i = tid; i < BTILE / 16; i += NTH)
            cpasync16(dst + i * 16, src + i);
    };
    float xg[16];
    auto gatherA = [&](int ch) {
        int k0 = ch * 64;
        int kk = k0 >> logC;
        int c0 = k0 & (C - 1);
        int ky = kk / 3, kx = kk - ky * 3;
        int iy = ay + ky - 1, ix = ax + kx - 1;
        bool v = aok && ((unsigned)iy < (unsigned)F) && ((unsigned)ix < (unsigned)F);
        const float* bp = fb0 + (size_t)(c0 + kq * 16) * FF + iy * F + ix;
        #pragma unroll
        for (int j = 0; j < 16; j++)
            xg[j] = v ? __ldg(bp + (size_t)j * FF) : 0.f;
    };
    auto storeA = [&](int buf) {
        uint32_t base = smb + buf * BUFSZ + A_OFF;
        uint32_t h[8];
        #pragma unroll
        for (int j = 0; j < 8; j++) h[j] = pack_h2(xg[j * 2], xg[j * 2 + 1]);
        // 16 halves = 32 bytes = granules 2*kq and 2*kq+1
        #pragma unroll
        for (int g = 0; g < 2; g++) {
            uint32_t off = swz((uint32_t)arow, (uint32_t)(kq * 2 + g));
            asm volatile("st.shared.v4.b32 [%0], {%1,%2,%3,%4};"
                         :: "r"(base + off),
                            "r"(h[g * 4 + 0]), "r"(h[g * 4 + 1]),
                            "r"(h[g * 4 + 2]), "r"(h[g * 4 + 3])
                         : "memory");
        }
    };
    auto compute = [&](int buf) {
        const uint32_t aB = smb + buf * BUFSZ + A_OFF;
        const uint32_t bB = smb + buf * BUFSZ + B_OFF;
        // hoisted per-lane row bases + swizzle masks
        uint32_t abase[2], amask[2];
        #pragma unroll
        for (int mt = 0; mt < 2; mt++) {
            uint32_t r = (uint32_t)(mg * 32 + mt * 16 + a_mloc);
            abase[mt] = aB + r * RS;
            amask[mt] = r & 7u;
        }
        uint32_t bbase[3], bmask[3];
        #pragma unroll
        for (int p = 0; p < 2; p++) {
            uint32_t r = (uint32_t)((gbase + p * 2) * 8 + b_nloc);
            bbase[p] = bB + r * RS;
            bmask[p] = r & 7u;
        }
        {
            uint32_t r = (uint32_t)((gbase + 4) * 8 + (lane & 7));
            bbase[2] = bB + r * RS;
            bmask[2] = r & 7u;
        }
        #pragma unroll
        for (int t = 0; t < 4; t++) {              // 4 k16 steps per chunk
            const uint32_t g0 = (uint32_t)t * 2;   // granule pair base
            uint32_t a0[4], a1[4];
            ldsm4(a0, abase[0] + (((g0 + a_kg) ^ amask[0]) << 4));
            ldsm4(a1, abase[1] + (((g0 + a_kg) ^ amask[1]) << 4));
            uint32_t b0[4], b1[4], b2[2];
            ldsm4(b0, bbase[0] + (((g0 + b_kg) ^ bmask[0]) << 4));
            ldsm4(b1, bbase[1] + (((g0 + b_kg) ^ bmask[1]) << 4));
            ldsm2(b2, bbase[2] + (((g0 + b_kg) ^ bmask[2]) << 4));
            mma_f16(acc[0][0], a0, b0);
            mma_f16(acc[1][0], a1, b0);
            mma_f16(acc[0][1], a0, b0 + 2);
            mma_f16(acc[1][1], a1, b0 + 2);
            mma_f16(acc[0][2], a0, b1);
            mma_f16(acc[1][2], a1, b1);
            mma_f16(acc[0][3], a0, b1 + 2);
            mma_f16(acc[1][3], a1, b1 + 2);
            mma_f16(acc[0][4], a0, b2);
            mma_f16(acc[1][4], a1, b2);
        }
    };

    // ---------------- pipeline ----------------
    copyB(0, 0);
    cpcommit();
    gatherA(0);
    storeA(0);
    cpwait0();
    __syncthreads();

    for (int ch = 0; ch < nch; ch++) {
        int cur = ch & 1;
        bool pf = (ch + 1 < nch);
        if (pf) {
            copyB(ch + 1, cur ^ 1);
            cpcommit();
            gatherA(ch + 1);        // LDGs in flight during MMAs
        }
        compute(cur);
        if (pf) storeA(cur ^ 1);    // convert + STS after MMAs
        cpwait0();
        __syncthreads();
    }
    __syncthreads();                // all compute done before Dsm overlays buffers

    // ---- write accumulators to smem D[128][DSTRIDE] ----
    #pragma unroll
    for (int mt = 0; mt < 2; mt++)
        #pragma unroll
        for (int nt = 0; nt < 5; nt++) {
            int r = mg * 32 + mt * 16 + (lane >> 2);
            int c = (gbase + nt) * 8 + (lane & 3) * 2;
            Dsm[r * DSTRIDE + c]           = acc[mt][nt][0];
            Dsm[r * DSTRIDE + c + 1]       = acc[mt][nt][1];
            Dsm[(r + 8) * DSTRIDE + c]     = acc[mt][nt][2];
            Dsm[(r + 8) * DSTRIDE + c + 1] = acc[mt][nt][3];
        }
    __syncthreads();

    // ---- per-pixel bias + decode + softmax ----
    if (tid < 128) {
        int n = pix0 + tid;
        if (n < N) {
            const float* drow = Dsm + tid * DSTRIDE;
            int b = n / FF;
            int r = n - b * FF;
            int pbase = d_poff[s] + r * 6;
            float* ob = out + ((size_t)b * NUM_PRIORS + pbase) * 25;
            const float* lb = P.lb[s];
            const float* cb = P.cb[s];
            #pragma unroll
            for (int pic = 0; pic < 6; pic++) {
                const float* pr = priors + (size_t)(pbase + pic) * 4;
                float prx = __ldg(pr + 0), pry = __ldg(pr + 1);
                float prz = __ldg(pr + 2), prw = __ldg(pr + 3);
                float lx = drow[pic * 4 + 0] + __ldg(lb + pic * 4 + 0);
                float ly = drow[pic * 4 + 1] + __ldg(lb + pic * 4 + 1);
                float lw_ = drow[pic * 4 + 2] + __ldg(lb + pic * 4 + 2);
                float lh_ = drow[pic * 4 + 3] + __ldg(lb + pic * 4 + 3);
                float cx = prx + lx * 0.1f * prz;
                float cy = pry + ly * 0.1f * prw;
                float w = prz * expf(lw_ * 0.2f);
                float h = prw * expf(lh_ * 0.2f);
                float mnx = cx - 0.5f * w;
                float mny = cy - 0.5f * h;
                float* o = ob + pic * 25;
                o[0] = mnx; o[1] = mny; o[2] = mnx + w; o[3] = mny + h;

                float vv[21];
                float mx = -1e30f;
                #pragma unroll
                for (int c2 = 0; c2 < 21; c2++) {
                    vv[c2] = drow[24 + pic * 21 + c2] + __ldg(cb + pic * 21 + c2);
                    mx = fmaxf(mx, vv[c2]);
                }
                float ssum = 0.f;
                #pragma unroll
                for (int c2 = 0; c2 < 21; c2++) { vv[c2] = expf(vv[c2] - mx); ssum += vv[c2]; }
                float inv = 1.f / ssum;
                #pragma unroll
                for (int c2 = 0; c2 < 21; c2++) o[4 + c2] = vv[c2] * inv;
            }
        }
    }
}

// ---------------------------------------------------------------------------
extern "C" void kernel_launch(void* const* d_in, const int* in_sizes, int n_in,
                              void* d_out, int out_size)
{
    CParams cp;
    WParams wp;
    const float* priors;

    bool interleaved = (n_in == 31) && (in_sizes[2] == 24);
    if (interleaved) {
        for (int s = 0; s < 6; s++) {
            cp.feat[s] = (const float*)d_in[s * 5 + 0];
            wp.lw[s]   = (const float*)d_in[s * 5 + 1];
            cp.lb[s]   = (const float*)d_in[s * 5 + 2];
            wp.cw[s]   = (const float*)d_in[s * 5 + 3];
            cp.cb[s]   = (const float*)d_in[s * 5 + 4];
        }
        priors = (const float*)d_in[30];
    } else {
        for (int s = 0; s < 6; s++) {
            cp.feat[s] = (const float*)d_in[s];
            wp.lw[s]   = (const float*)d_in[6 + s];
            cp.lb[s]   = (const float*)d_in[12 + s];
            wp.cw[s]   = (const float*)d_in[18 + s];
            cp.cb[s]   = (const float*)d_in[24 + s];
        }
        priors = (const float*)d_in[30];
    }

    cudaFuncSetAttribute(ssd_f16_kernel,
                         cudaFuncAttributeMaxDynamicSharedMemorySize, SMEM_BYTES);

    prep_weights<<<TOTAL_WCHUNKS, 256>>>(wp);
    ssd_f16_kernel<<<TOTAL_BLOCKS, NTH, SMEM_BYTES>>>(cp, priors, (float*)d_out);
}